// round 1
// baseline (speedup 1.0000x reference)
#include <cuda_runtime.h>
#include <math.h>

#define S_LEN  4096
#define HDIM   2048
#define NHQ    8
#define NKV    2
#define DH     256
#define WINDOW 512

// Scratch (device globals: allocation-free rule)
__device__ float g_q[S_LEN * NHQ * DH];     // 32 MB
__device__ float g_k[S_LEN * NKV * DH];     // 8 MB
__device__ float g_v[S_LEN * NKV * DH];     // 8 MB
__device__ float g_attn[S_LEN * NHQ * DH];  // 32 MB

// ---------------------------------------------------------------------------
// SGEMM: C[M,N] = A[M,K] @ B[K,N], row-major, all dims multiples of tile sizes
// 128x128 tile, BK=8, 256 threads, 8x8 per thread.
// ---------------------------------------------------------------------------
__global__ __launch_bounds__(256) void sgemm_kernel(
    const float* __restrict__ A, const float* __restrict__ B,
    float* __restrict__ C, int M, int N, int K)
{
    __shared__ float As[8][128];
    __shared__ float Bs[8][128];

    const int tid  = threadIdx.x;
    const int brow = blockIdx.y * 128;
    const int bcol = blockIdx.x * 128;

    const int a_row  = tid >> 1;          // 0..127
    const int a_col4 = (tid & 1) * 4;     // 0 or 4
    const int b_row  = tid >> 5;          // 0..7
    const int b_col4 = (tid & 31) * 4;    // 0..124

    const int tx = tid & 15;
    const int ty = tid >> 4;

    float acc[8][8];
#pragma unroll
    for (int i = 0; i < 8; i++)
#pragma unroll
        for (int j = 0; j < 8; j++) acc[i][j] = 0.f;

    for (int k0 = 0; k0 < K; k0 += 8) {
        float4 av = *(const float4*)&A[(size_t)(brow + a_row) * K + k0 + a_col4];
        As[a_col4 + 0][a_row] = av.x;
        As[a_col4 + 1][a_row] = av.y;
        As[a_col4 + 2][a_row] = av.z;
        As[a_col4 + 3][a_row] = av.w;
        *(float4*)&Bs[b_row][b_col4] =
            *(const float4*)&B[(size_t)(k0 + b_row) * N + bcol + b_col4];
        __syncthreads();

#pragma unroll
        for (int kk = 0; kk < 8; kk++) {
            float4 a0 = *(const float4*)&As[kk][ty * 8];
            float4 a1 = *(const float4*)&As[kk][ty * 8 + 4];
            float4 b0 = *(const float4*)&Bs[kk][tx * 8];
            float4 b1 = *(const float4*)&Bs[kk][tx * 8 + 4];
            float ar[8] = {a0.x, a0.y, a0.z, a0.w, a1.x, a1.y, a1.z, a1.w};
            float br[8] = {b0.x, b0.y, b0.z, b0.w, b1.x, b1.y, b1.z, b1.w};
#pragma unroll
            for (int i = 0; i < 8; i++)
#pragma unroll
                for (int j = 0; j < 8; j++) acc[i][j] += ar[i] * br[j];
        }
        __syncthreads();
    }

#pragma unroll
    for (int i = 0; i < 8; i++) {
        float* crow = &C[(size_t)(brow + ty * 8 + i) * N + bcol + tx * 8];
        *(float4*)&crow[0] = make_float4(acc[i][0], acc[i][1], acc[i][2], acc[i][3]);
        *(float4*)&crow[4] = make_float4(acc[i][4], acc[i][5], acc[i][6], acc[i][7]);
    }
}

// ---------------------------------------------------------------------------
// Fused RMSNorm (+ optional weight) + RoPE (for q,k).
// grid = (S, 12): slots 0-7 = q heads, 8-9 = k heads, 10-11 = v heads
// block = 256 threads (one per dim)
// ---------------------------------------------------------------------------
__global__ __launch_bounds__(256) void norm_rope_kernel(
    const float* __restrict__ qw, const float* __restrict__ kw,
    const float* __restrict__ cosb, const float* __restrict__ sinb)
{
    const int s    = blockIdx.x;
    const int slot = blockIdx.y;
    const int d    = threadIdx.x;

    float* base;
    const float* w = nullptr;
    bool do_rope = true;
    if (slot < 8)       { base = g_q + (size_t)s * (NHQ * DH) + slot * DH;        w = qw; }
    else if (slot < 10) { base = g_k + (size_t)s * (NKV * DH) + (slot - 8) * DH;  w = kw; }
    else                { base = g_v + (size_t)s * (NKV * DH) + (slot - 10) * DH; do_rope = false; }

    float x  = base[d];
    float v2 = x * x;
#pragma unroll
    for (int o = 16; o > 0; o >>= 1) v2 += __shfl_xor_sync(0xffffffffu, v2, o);

    __shared__ float wsum[8];
    __shared__ float ys[256];
    const int warp = d >> 5, lane = d & 31;
    if (lane == 0) wsum[warp] = v2;
    __syncthreads();
    float tot = 0.f;
#pragma unroll
    for (int i = 0; i < 8; i++) tot += wsum[i];

    float y = x * rsqrtf(tot * (1.0f / 256.0f) + 1e-6f);
    if (w) y *= w[d];

    if (do_rope) {
        ys[d] = y;
        __syncthreads();
        float rot = (d < 128) ? -ys[d + 128] : ys[d - 128];
        y = y * cosb[(size_t)s * DH + d] + rot * sinb[(size_t)s * DH + d];
    }
    base[d] = y;
}

// ---------------------------------------------------------------------------
// Sliding-window causal attention (flash-style, fp32).
// grid = (S/64, NH), block = 256 threads.
// Thread t: qi = t&63 (query within tile), dg = t>>6 (64-dim chunk).
// SMEM: K tile 64x256 (64KB) + V tile 64x256 (64KB) + score partials 4x64x64 (64KB)
// ---------------------------------------------------------------------------
__global__ __launch_bounds__(256) void attn_kernel(float* __restrict__ gout)
{
    extern __shared__ float sm[];
    float* Ks = sm;                 // 64*256
    float* Vs = sm + 64 * 256;      // 64*256
    float* Sp = sm + 2 * 64 * 256;  // 4*64*64 (partials; slice 0 reused for scores)

    const int tid = threadIdx.x;
    const int qt  = blockIdx.x;
    const int h   = blockIdx.y;
    const int kvh = h >> 2;   // G = 4
    const int q0  = qt * 64;
    const int qi  = tid & 63;
    const int dg  = tid >> 6;
    const int qglob = q0 + qi;

    // Load q into registers (64 dims of this thread's chunk)
    float qreg[64];
    {
        const float* qptr = g_q + (size_t)qglob * (NHQ * DH) + h * DH + dg * 64;
#pragma unroll
        for (int i = 0; i < 64; i += 4) {
            float4 t4 = *(const float4*)(qptr + i);
            qreg[i] = t4.x; qreg[i + 1] = t4.y; qreg[i + 2] = t4.z; qreg[i + 3] = t4.w;
        }
    }

    float acc[64];
#pragma unroll
    for (int i = 0; i < 64; i++) acc[i] = 0.f;
    float m = -1e30f, l = 0.f;

    const int t0 = max(0, qt - 8);
    for (int kt = t0; kt <= qt; kt++) {
        const int kbase = kt * 64;

        // Cooperative load of K and V tiles (64 rows x 256 floats each)
        for (int i = tid; i < 64 * 64; i += 256) {
            int row = i >> 6;
            int c4  = (i & 63) * 4;
            size_t goff = (size_t)(kbase + row) * (NKV * DH) + kvh * DH + c4;
            *(float4*)(Ks + row * 256 + c4) = *(const float4*)(g_k + goff);
            *(float4*)(Vs + row * 256 + c4) = *(const float4*)(g_v + goff);
        }
        __syncthreads();

        // Partial scores: this thread's 64-dim slice, for all 64 keys
        float* myp = Sp + dg * 64 * 64;
        for (int kj = 0; kj < 64; kj++) {
            const float* kr = Ks + kj * 256 + dg * 64;
            float s0 = 0.f, s1 = 0.f, s2 = 0.f, s3 = 0.f;
#pragma unroll
            for (int i = 0; i < 64; i += 4) {
                float4 k4 = *(const float4*)(kr + i);
                s0 += qreg[i]     * k4.x;
                s1 += qreg[i + 1] * k4.y;
                s2 += qreg[i + 2] * k4.z;
                s3 += qreg[i + 3] * k4.w;
            }
            myp[kj * 64 + qi] = (s0 + s1) + (s2 + s3);
        }
        __syncthreads();

        // Reduce partials across the 4 dgroups + apply sliding-window mask
        for (int i = tid; i < 4096; i += 256) {
            float v = Sp[i] + Sp[4096 + i] + Sp[8192 + i] + Sp[12288 + i];
            int kj = i >> 6, qq = i & 63;
            int kk = kbase + kj, qg = q0 + qq;
            bool valid = (kk <= qg) && (qg - kk < WINDOW);
            Sp[i] = valid ? v : -1e30f;
        }
        __syncthreads();

        // Online softmax + PV (each of the 4 dgroup threads per query keeps
        // redundant identical copies of m, l)
        float mt = m;
        for (int kj = 0; kj < 64; kj++) mt = fmaxf(mt, Sp[kj * 64 + qi]);
        float c = __expf(m - mt);
        m = mt;
        l *= c;
#pragma unroll
        for (int i = 0; i < 64; i++) acc[i] *= c;

        for (int kj = 0; kj < 64; kj++) {
            float sv = Sp[kj * 64 + qi];
            float p  = (sv > -1e29f) ? __expf(sv - mt) : 0.f;
            l += p;
            const float* vr = Vs + kj * 256 + dg * 64;
#pragma unroll
            for (int i = 0; i < 64; i += 4) {
                float4 v4 = *(const float4*)(vr + i);
                acc[i]     += p * v4.x;
                acc[i + 1] += p * v4.y;
                acc[i + 2] += p * v4.z;
                acc[i + 3] += p * v4.w;
            }
        }
        __syncthreads();
    }

    // Stage normalized output through SMEM (reuse Ks) for coalesced store
    float inv_l = 1.f / l;
#pragma unroll
    for (int i = 0; i < 64; i++) Ks[qi * 256 + dg * 64 + i] = acc[i] * inv_l;
    __syncthreads();

    for (int i = tid; i < 64 * 64; i += 256) {
        int row = i >> 6;
        int c4  = (i & 63) * 4;
        *(float4*)(gout + (size_t)(q0 + row) * (NHQ * DH) + h * DH + c4) =
            *(const float4*)(Ks + row * 256 + c4);
    }
}

// ---------------------------------------------------------------------------
extern "C" void kernel_launch(void* const* d_in, const int* in_sizes, int n_in,
                              void* d_out, int out_size)
{
    (void)in_sizes; (void)n_in; (void)out_size;
    const float* hs   = (const float*)d_in[0];
    const float* w_q  = (const float*)d_in[1];
    const float* w_k  = (const float*)d_in[2];
    const float* w_v  = (const float*)d_in[3];
    const float* w_o  = (const float*)d_in[4];
    const float* qw   = (const float*)d_in[5];
    const float* kw   = (const float*)d_in[6];
    const float* cosb = (const float*)d_in[7];
    const float* sinb = (const float*)d_in[8];
    float* out = (float*)d_out;

    float *gq, *gk, *gv, *ga;
    cudaGetSymbolAddress((void**)&gq, g_q);
    cudaGetSymbolAddress((void**)&gk, g_k);
    cudaGetSymbolAddress((void**)&gv, g_v);
    cudaGetSymbolAddress((void**)&ga, g_attn);

    static bool attr_set = false;
    if (!attr_set) {
        cudaFuncSetAttribute(attn_kernel,
                             cudaFuncAttributeMaxDynamicSharedMemorySize,
                             (2 * 64 * 256 + 4 * 64 * 64) * sizeof(float));
        attr_set = true;
    }

    // QKV projections
    sgemm_kernel<<<dim3(HDIM / 128, S_LEN / 128), 256>>>(hs, w_q, gq, S_LEN, NHQ * DH, HDIM);
    sgemm_kernel<<<dim3((NKV * DH) / 128, S_LEN / 128), 256>>>(hs, w_k, gk, S_LEN, NKV * DH, HDIM);
    sgemm_kernel<<<dim3((NKV * DH) / 128, S_LEN / 128), 256>>>(hs, w_v, gv, S_LEN, NKV * DH, HDIM);

    // RMSNorm + RoPE
    norm_rope_kernel<<<dim3(S_LEN, NHQ + 2 * NKV), 256>>>(qw, kw, cosb, sinb);

    // Sliding-window attention
    attn_kernel<<<dim3(S_LEN / 64, NHQ), 256,
                  (2 * 64 * 256 + 4 * 64 * 64) * sizeof(float)>>>(ga);

    // Output projection
    sgemm_kernel<<<dim3(HDIM / 128, S_LEN / 128), 256>>>(ga, w_o, out, S_LEN, HDIM, HDIM);
}

// round 4
// speedup vs baseline: 1.3014x; 1.3014x over previous
#include <cuda_runtime.h>
#include <math.h>

#define S_LEN  4096
#define HDIM   2048
#define NHQ    8
#define NKV    2
#define DH     256
#define WINDOW 512

// Scratch (device globals: allocation-free rule)
__device__ float g_q[S_LEN * NHQ * DH];     // 32 MB
__device__ float g_k[S_LEN * NKV * DH];     // 8 MB
__device__ float g_v[S_LEN * NKV * DH];     // 8 MB
__device__ float g_attn[S_LEN * NHQ * DH];  // 32 MB

// ===========================================================================
// Helpers
// ===========================================================================
__device__ __forceinline__ unsigned smem_u32(const void* p) {
    unsigned a;
    asm("{ .reg .u64 t; cvta.to.shared.u64 t, %1; cvt.u32.u64 %0, t; }"
        : "=r"(a) : "l"(p));
    return a;
}

#define CP_ASYNC16(dst, src) \
    asm volatile("cp.async.cg.shared.global [%0], [%1], 16;" :: "r"(dst), "l"(src) : "memory")
#define CP_COMMIT() asm volatile("cp.async.commit_group;" ::: "memory")

__device__ __forceinline__ unsigned f2tf32(float x) {
    unsigned u;
    asm("cvt.rna.tf32.f32 %0, %1;" : "=r"(u) : "f"(x));
    return u;
}

// Split x into hi (tf32) and lo (tf32 of residual): x ~= hi + lo
__device__ __forceinline__ void tf32_split(float x, unsigned& hi, unsigned& lo) {
    hi = f2tf32(x);
    lo = f2tf32(x - __uint_as_float(hi));
}

__device__ __forceinline__ void mma_tf32(float* d, const unsigned* a, const unsigned* b) {
    asm volatile(
        "mma.sync.aligned.m16n8k8.row.col.f32.tf32.tf32.f32 "
        "{%0,%1,%2,%3}, {%4,%5,%6,%7}, {%8,%9}, {%0,%1,%2,%3};"
        : "+f"(d[0]), "+f"(d[1]), "+f"(d[2]), "+f"(d[3])
        : "r"(a[0]), "r"(a[1]), "r"(a[2]), "r"(a[3]), "r"(b[0]), "r"(b[1]));
}

// ===========================================================================
// 3xTF32 mma.sync GEMM: C[M,N] = A[M,K] @ B[K,N], fp32 in/out, ~fp32 accuracy
// via error-compensated split: a*b ~= ah*bh + ah*bl + al*bh.
// BM=128, BN=128, BK=32. 256 threads = 8 warps in 4(m) x 2(n).
// Warp tile 32x64: 2 m-frags x 8 n-frags of m16n8k8, 4 k-steps per chunk.
// SMEM: As[m][k] stride 36 floats, Bs[k][n] stride 132 floats.
// 3-stage cp.async pipeline.
// ===========================================================================
#define A_STRIDE 36
#define B_STRIDE 132
#define A_BYTES  (128 * A_STRIDE * 4)     // 18432
#define B_BYTES  (32 * B_STRIDE * 4)      // 16896
#define STAGE_BYTES (A_BYTES + B_BYTES)   // 35328
#define GSTAGES 3
#define GEMM_SMEM (GSTAGES * STAGE_BYTES) // 105984

__global__ __launch_bounds__(256) void mma_gemm_kernel(
    const float* __restrict__ A, const float* __restrict__ B,
    float* __restrict__ C, int M, int N, int K)
{
    extern __shared__ char gsm[];
    const unsigned sbase = smem_u32(gsm);

    const int tid  = threadIdx.x;
    const int wid  = tid >> 5;
    const int lane = tid & 31;
    const int g    = lane >> 2;     // groupID 0..7
    const int t4   = lane & 3;      // threadID_in_group 0..3
    const int wm   = wid & 3;       // warp m index 0..3
    const int wn   = wid >> 2;      // warp n index 0..1

    const int brow = blockIdx.y * 128;
    const int bcol = blockIdx.x * 128;
    const int nchunks = K / 32;

    float acc[2][8][4];
#pragma unroll
    for (int mf = 0; mf < 2; mf++)
#pragma unroll
        for (int nf = 0; nf < 8; nf++)
#pragma unroll
            for (int r = 0; r < 4; r++) acc[mf][nf][r] = 0.f;

    auto fill_stage = [&](int c, int s) {
        const int k0 = c * 32;
        const unsigned sa = sbase + s * STAGE_BYTES;
        const unsigned sb = sa + A_BYTES;
#pragma unroll
        for (int j = 0; j < 4; j++) {
            int i = tid + j * 256;      // 0..1023
            int r = i >> 3, u = i & 7;
            CP_ASYNC16(sa + (unsigned)(r * (A_STRIDE * 4) + u * 16),
                       A + (size_t)(brow + r) * K + k0 + u * 4);
        }
#pragma unroll
        for (int j = 0; j < 4; j++) {
            int i = tid + j * 256;
            int kk = i >> 5, un = i & 31;
            CP_ASYNC16(sb + (unsigned)(kk * (B_STRIDE * 4) + un * 16),
                       B + (size_t)(k0 + kk) * N + bcol + un * 4);
        }
        CP_COMMIT();
    };

#pragma unroll
    for (int c = 0; c < GSTAGES; c++) fill_stage(c, c);

#pragma unroll 1
    for (int c = 0; c < nchunks; c++) {
        const int s = c % GSTAGES;
        const int rem = nchunks - 1 - c;
        if (rem >= 2)      asm volatile("cp.async.wait_group 2;" ::: "memory");
        else if (rem == 1) asm volatile("cp.async.wait_group 1;" ::: "memory");
        else               asm volatile("cp.async.wait_group 0;" ::: "memory");
        __syncthreads();

        const float* As = (const float*)(gsm + s * STAGE_BYTES);
        const float* Bs = (const float*)(gsm + s * STAGE_BYTES + A_BYTES);

#pragma unroll
        for (int ks = 0; ks < 4; ks++) {
            const int kk = ks * 8 + t4;
            unsigned ah[2][4], al[2][4];
#pragma unroll
            for (int mf = 0; mf < 2; mf++) {
                const int r0 = wm * 32 + mf * 16 + g;
                tf32_split(As[r0 * A_STRIDE + kk],           ah[mf][0], al[mf][0]);
                tf32_split(As[(r0 + 8) * A_STRIDE + kk],     ah[mf][1], al[mf][1]);
                tf32_split(As[r0 * A_STRIDE + kk + 4],       ah[mf][2], al[mf][2]);
                tf32_split(As[(r0 + 8) * A_STRIDE + kk + 4], ah[mf][3], al[mf][3]);
            }
#pragma unroll
            for (int nf = 0; nf < 8; nf++) {
                const int n = wn * 64 + nf * 8 + g;
                unsigned bh[2], bl[2];
                tf32_split(Bs[kk * B_STRIDE + n],       bh[0], bl[0]);
                tf32_split(Bs[(kk + 4) * B_STRIDE + n], bh[1], bl[1]);
#pragma unroll
                for (int mf = 0; mf < 2; mf++) {
                    mma_tf32(acc[mf][nf], ah[mf], bh);
                    mma_tf32(acc[mf][nf], ah[mf], bl);
                    mma_tf32(acc[mf][nf], al[mf], bh);
                }
            }
        }
        __syncthreads();

        if (c + GSTAGES < nchunks) fill_stage(c + GSTAGES, s);
    }

    // Epilogue: direct register -> gmem (float2 pairs)
#pragma unroll
    for (int mf = 0; mf < 2; mf++) {
        const int r0 = brow + wm * 32 + mf * 16 + g;
#pragma unroll
        for (int nf = 0; nf < 8; nf++) {
            const int cc = bcol + wn * 64 + nf * 8 + 2 * t4;
            *(float2*)&C[(size_t)r0 * N + cc] =
                make_float2(acc[mf][nf][0], acc[mf][nf][1]);
            *(float2*)&C[(size_t)(r0 + 8) * N + cc] =
                make_float2(acc[mf][nf][2], acc[mf][nf][3]);
        }
    }
}

// ===========================================================================
// Fused RMSNorm (+ optional weight) + RoPE
// ===========================================================================
__global__ __launch_bounds__(256) void norm_rope_kernel(
    const float* __restrict__ qw, const float* __restrict__ kw,
    const float* __restrict__ cosb, const float* __restrict__ sinb)
{
    const int s    = blockIdx.x;
    const int slot = blockIdx.y;
    const int d    = threadIdx.x;

    float* basep;
    const float* w = nullptr;
    bool do_rope = true;
    if (slot < 8)       { basep = g_q + (size_t)s * (NHQ * DH) + slot * DH;        w = qw; }
    else if (slot < 10) { basep = g_k + (size_t)s * (NKV * DH) + (slot - 8) * DH;  w = kw; }
    else                { basep = g_v + (size_t)s * (NKV * DH) + (slot - 10) * DH; do_rope = false; }

    float x  = basep[d];
    float v2 = x * x;
#pragma unroll
    for (int o = 16; o > 0; o >>= 1) v2 += __shfl_xor_sync(0xffffffffu, v2, o);

    __shared__ float wsum[8];
    __shared__ float ys[256];
    const int warp = d >> 5, lane = d & 31;
    if (lane == 0) wsum[warp] = v2;
    __syncthreads();
    float tot = 0.f;
#pragma unroll
    for (int i = 0; i < 8; i++) tot += wsum[i];

    float y = x * rsqrtf(tot * (1.0f / 256.0f) + 1e-6f);
    if (w) y *= w[d];

    if (do_rope) {
        ys[d] = y;
        __syncthreads();
        float rot = (d < 128) ? -ys[d + 128] : ys[d - 128];
        y = y * cosb[(size_t)s * DH + d] + rot * sinb[(size_t)s * DH + d];
    }
    basep[d] = y;
}

// ===========================================================================
// Sliding-window causal attention (fp32, unchanged)
// ===========================================================================
__global__ __launch_bounds__(256) void attn_kernel(float* __restrict__ gout)
{
    extern __shared__ float sm[];
    float* Ks = sm;
    float* Vs = sm + 64 * 256;
    float* Sp = sm + 2 * 64 * 256;

    const int tid = threadIdx.x;
    const int qt  = blockIdx.x;
    const int h   = blockIdx.y;
    const int kvh = h >> 2;
    const int q0  = qt * 64;
    const int qi  = tid & 63;
    const int dg  = tid >> 6;
    const int qglob = q0 + qi;

    float qreg[64];
    {
        const float* qptr = g_q + (size_t)qglob * (NHQ * DH) + h * DH + dg * 64;
#pragma unroll
        for (int i = 0; i < 64; i += 4) {
            float4 t4 = *(const float4*)(qptr + i);
            qreg[i] = t4.x; qreg[i + 1] = t4.y; qreg[i + 2] = t4.z; qreg[i + 3] = t4.w;
        }
    }

    float acc[64];
#pragma unroll
    for (int i = 0; i < 64; i++) acc[i] = 0.f;
    float m = -1e30f, l = 0.f;

    const int t0 = max(0, qt - 8);
    for (int kt = t0; kt <= qt; kt++) {
        const int kbase = kt * 64;

        for (int i = tid; i < 64 * 64; i += 256) {
            int row = i >> 6;
            int c4  = (i & 63) * 4;
            size_t goff = (size_t)(kbase + row) * (NKV * DH) + kvh * DH + c4;
            *(float4*)(Ks + row * 256 + c4) = *(const float4*)(g_k + goff);
            *(float4*)(Vs + row * 256 + c4) = *(const float4*)(g_v + goff);
        }
        __syncthreads();

        float* myp = Sp + dg * 64 * 64;
        for (int kj = 0; kj < 64; kj++) {
            const float* kr = Ks + kj * 256 + dg * 64;
            float s0 = 0.f, s1 = 0.f, s2 = 0.f, s3 = 0.f;
#pragma unroll
            for (int i = 0; i < 64; i += 4) {
                float4 k4 = *(const float4*)(kr + i);
                s0 += qreg[i]     * k4.x;
                s1 += qreg[i + 1] * k4.y;
                s2 += qreg[i + 2] * k4.z;
                s3 += qreg[i + 3] * k4.w;
            }
            myp[kj * 64 + qi] = (s0 + s1) + (s2 + s3);
        }
        __syncthreads();

        for (int i = tid; i < 4096; i += 256) {
            float v = Sp[i] + Sp[4096 + i] + Sp[8192 + i] + Sp[12288 + i];
            int kj = i >> 6, qq = i & 63;
            int kk = kbase + kj, qg = q0 + qq;
            bool valid = (kk <= qg) && (qg - kk < WINDOW);
            Sp[i] = valid ? v : -1e30f;
        }
        __syncthreads();

        float mt = m;
        for (int kj = 0; kj < 64; kj++) mt = fmaxf(mt, Sp[kj * 64 + qi]);
        float c = __expf(m - mt);
        m = mt;
        l *= c;
#pragma unroll
        for (int i = 0; i < 64; i++) acc[i] *= c;

        for (int kj = 0; kj < 64; kj++) {
            float sv = Sp[kj * 64 + qi];
            float p  = (sv > -1e29f) ? __expf(sv - mt) : 0.f;
            l += p;
            const float* vr = Vs + kj * 256 + dg * 64;
#pragma unroll
            for (int i = 0; i < 64; i += 4) {
                float4 v4 = *(const float4*)(vr + i);
                acc[i]     += p * v4.x;
                acc[i + 1] += p * v4.y;
                acc[i + 2] += p * v4.z;
                acc[i + 3] += p * v4.w;
            }
        }
        __syncthreads();
    }

    float inv_l = 1.f / l;
#pragma unroll
    for (int i = 0; i < 64; i++) Ks[qi * 256 + dg * 64 + i] = acc[i] * inv_l;
    __syncthreads();

    for (int i = tid; i < 64 * 64; i += 256) {
        int row = i >> 6;
        int c4  = (i & 63) * 4;
        *(float4*)(gout + (size_t)(q0 + row) * (NHQ * DH) + h * DH + c4) =
            *(const float4*)(Ks + row * 256 + c4);
    }
}

// ===========================================================================
extern "C" void kernel_launch(void* const* d_in, const int* in_sizes, int n_in,
                              void* d_out, int out_size)
{
    (void)in_sizes; (void)n_in; (void)out_size;
    const float* hs   = (const float*)d_in[0];
    const float* w_q  = (const float*)d_in[1];
    const float* w_k  = (const float*)d_in[2];
    const float* w_v  = (const float*)d_in[3];
    const float* w_o  = (const float*)d_in[4];
    const float* qw   = (const float*)d_in[5];
    const float* kw   = (const float*)d_in[6];
    const float* cosb = (const float*)d_in[7];
    const float* sinb = (const float*)d_in[8];
    float* out = (float*)d_out;

    float *gq, *gk, *gv, *ga;
    cudaGetSymbolAddress((void**)&gq, g_q);
    cudaGetSymbolAddress((void**)&gk, g_k);
    cudaGetSymbolAddress((void**)&gv, g_v);
    cudaGetSymbolAddress((void**)&ga, g_attn);

    const int attn_smem = (2 * 64 * 256 + 4 * 64 * 64) * sizeof(float);
    cudaFuncSetAttribute(mma_gemm_kernel, cudaFuncAttributeMaxDynamicSharedMemorySize, GEMM_SMEM);
    cudaFuncSetAttribute(attn_kernel, cudaFuncAttributeMaxDynamicSharedMemorySize, attn_smem);

    // QKV projections (3xTF32 mma.sync)
    mma_gemm_kernel<<<dim3((NHQ * DH) / 128, S_LEN / 128), 256, GEMM_SMEM>>>(
        hs, w_q, gq, S_LEN, NHQ * DH, HDIM);
    mma_gemm_kernel<<<dim3((NKV * DH) / 128, S_LEN / 128), 256, GEMM_SMEM>>>(
        hs, w_k, gk, S_LEN, NKV * DH, HDIM);
    mma_gemm_kernel<<<dim3((NKV * DH) / 128, S_LEN / 128), 256, GEMM_SMEM>>>(
        hs, w_v, gv, S_LEN, NKV * DH, HDIM);

    // RMSNorm + RoPE
    norm_rope_kernel<<<dim3(S_LEN, NHQ + 2 * NKV), 256>>>(qw, kw, cosb, sinb);

    // Sliding-window attention
    attn_kernel<<<dim3(S_LEN / 64, NHQ), 256, attn_smem>>>(ga);

    // Output projection (3xTF32 mma.sync)
    mma_gemm_kernel<<<dim3(HDIM / 128, S_LEN / 128), 256, GEMM_SMEM>>>(
        ga, w_o, out, S_LEN, HDIM, HDIM);
}

// round 5
// speedup vs baseline: 1.5061x; 1.1573x over previous
#include <cuda_runtime.h>
#include <cuda_bf16.h>
#include <math.h>

#define S_LEN  4096
#define HDIM   2048
#define NHQ    8
#define NKV    2
#define DH     256
#define WINDOW 512

// fp32 scratch
__device__ float g_q[S_LEN * NHQ * DH];     // 32 MB
__device__ float g_k[S_LEN * NKV * DH];     // 8 MB
__device__ float g_v[S_LEN * NKV * DH];     // 8 MB
__device__ float g_attn[S_LEN * NHQ * DH];  // 32 MB

// bf16 split scratch (hi/lo). g_a* reused: hs splits, then attn-out splits.
__device__ __nv_bfloat16 g_a0[S_LEN * HDIM];        // 16 MB
__device__ __nv_bfloat16 g_a1[S_LEN * HDIM];        // 16 MB
__device__ __nv_bfloat16 g_wq0[HDIM * HDIM];        // 8 MB  (transposed [N][K])
__device__ __nv_bfloat16 g_wq1[HDIM * HDIM];
__device__ __nv_bfloat16 g_wk0[(NKV * DH) * HDIM];  // 2 MB
__device__ __nv_bfloat16 g_wk1[(NKV * DH) * HDIM];
__device__ __nv_bfloat16 g_wv0[(NKV * DH) * HDIM];
__device__ __nv_bfloat16 g_wv1[(NKV * DH) * HDIM];
__device__ __nv_bfloat16 g_wo0[HDIM * HDIM];
__device__ __nv_bfloat16 g_wo1[HDIM * HDIM];

// ===========================================================================
// Helpers
// ===========================================================================
__device__ __forceinline__ unsigned smem_u32(const void* p) {
    unsigned a;
    asm("{ .reg .u64 t; cvta.to.shared.u64 t, %1; cvt.u32.u64 %0, t; }"
        : "=r"(a) : "l"(p));
    return a;
}

#define CP_ASYNC16(dst, src) \
    asm volatile("cp.async.cg.shared.global [%0], [%1], 16;" :: "r"(dst), "l"(src) : "memory")
#define CP_COMMIT() asm volatile("cp.async.commit_group;" ::: "memory")

__device__ __forceinline__ void bf16_split(float x, __nv_bfloat16& h, __nv_bfloat16& l) {
    h = __float2bfloat16_rn(x);
    l = __float2bfloat16_rn(x - __bfloat162float(h));
}

__device__ __forceinline__ void mma_bf16(float* d, const unsigned* a, const unsigned* b) {
    asm volatile(
        "mma.sync.aligned.m16n8k16.row.col.f32.bf16.bf16.f32 "
        "{%0,%1,%2,%3}, {%4,%5,%6,%7}, {%8,%9}, {%0,%1,%2,%3};"
        : "+f"(d[0]), "+f"(d[1]), "+f"(d[2]), "+f"(d[3])
        : "r"(a[0]), "r"(a[1]), "r"(a[2]), "r"(a[3]), "r"(b[0]), "r"(b[1]));
}

// ===========================================================================
// Split kernel: fp32 [n] -> hi/lo bf16 planar (same layout). 4 elems/thread.
// ===========================================================================
__global__ __launch_bounds__(256) void split_kernel(
    const float* __restrict__ in, __nv_bfloat16* __restrict__ o0,
    __nv_bfloat16* __restrict__ o1, int n)
{
    int i = (blockIdx.x * 256 + threadIdx.x) * 4;
    if (i >= n) return;
    float4 v = *(const float4*)(in + i);
    __nv_bfloat16 h0, l0, h1, l1, h2, l2, h3, l3;
    bf16_split(v.x, h0, l0); bf16_split(v.y, h1, l1);
    bf16_split(v.z, h2, l2); bf16_split(v.w, h3, l3);
    __nv_bfloat162* p0 = (__nv_bfloat162*)(o0 + i);
    __nv_bfloat162* p1 = (__nv_bfloat162*)(o1 + i);
    p0[0] = __nv_bfloat162(h0, h1); p0[1] = __nv_bfloat162(h2, h3);
    p1[0] = __nv_bfloat162(l0, l1); p1[1] = __nv_bfloat162(l2, l3);
}

// ===========================================================================
// Transpose-split kernel: fp32 B [K][N] -> hi/lo bf16 [N][K].
// 32x32 tile, block 32x8.
// ===========================================================================
__global__ __launch_bounds__(256) void tsplit_kernel(
    const float* __restrict__ in, __nv_bfloat16* __restrict__ o0,
    __nv_bfloat16* __restrict__ o1, int K, int N)
{
    __shared__ float tile[32][33];
    const int n0 = blockIdx.x * 32;
    const int k0 = blockIdx.y * 32;
    const int tx = threadIdx.x, ty = threadIdx.y;
#pragma unroll
    for (int j = 0; j < 4; j++)
        tile[ty + 8 * j][tx] = in[(size_t)(k0 + ty + 8 * j) * N + n0 + tx];
    __syncthreads();
#pragma unroll
    for (int j = 0; j < 4; j++) {
        int ny = ty + 8 * j;
        float x = tile[tx][ny];
        __nv_bfloat16 h, l;
        bf16_split(x, h, l);
        size_t off = (size_t)(n0 + ny) * K + k0 + tx;
        o0[off] = h;
        o1[off] = l;
    }
}

// ===========================================================================
// bf16x3 GEMM: C[M,N] = A[M,K] @ B[K,N] with A=(A0+A1), Bt=(B0+B1) splits.
// a*b ~= a0b0 + a0b1 + a1b0.  fp32 accumulate.
// BM=128, BN=128, BK=32. 256 threads = 8 warps (4 m x 2 n), warp tile 32x64.
// SMEM per stage: 4 arrays [128 rows][40 bf16] (32 data + 8 pad), 40960 B.
// 3-stage cp.async pipeline.
// ===========================================================================
#define ROW_E   40                          // bf16 elems per smem row
#define ROW_B   (ROW_E * 2)                 // 80 bytes
#define ARR_B   (128 * ROW_B)               // 10240 bytes per array
#define STAGE_B (4 * ARR_B)                 // 40960
#define GSTAGES 3
#define GEMM_SMEM (GSTAGES * STAGE_B)       // 122880

__global__ __launch_bounds__(256) void bf16_gemm_kernel(
    const __nv_bfloat16* __restrict__ A0, const __nv_bfloat16* __restrict__ A1,
    const __nv_bfloat16* __restrict__ B0, const __nv_bfloat16* __restrict__ B1,
    float* __restrict__ C, int M, int N, int K)
{
    extern __shared__ char gsm[];
    const unsigned sbase = smem_u32(gsm);

    const int tid  = threadIdx.x;
    const int wid  = tid >> 5;
    const int lane = tid & 31;
    const int g    = lane >> 2;
    const int t4   = lane & 3;
    const int wm   = wid & 3;
    const int wn   = wid >> 2;

    const int brow = blockIdx.y * 128;
    const int bcol = blockIdx.x * 128;
    const int nchunks = K / 32;

    float acc[2][8][4];
#pragma unroll
    for (int mf = 0; mf < 2; mf++)
#pragma unroll
        for (int nf = 0; nf < 8; nf++)
#pragma unroll
            for (int r = 0; r < 4; r++) acc[mf][nf][r] = 0.f;

    const __nv_bfloat16* srcs[4] = {A0, A1, B0, B1};

    auto fill_stage = [&](int c, int s) {
        const int k0 = c * 32;
        const unsigned st = sbase + s * STAGE_B;
#pragma unroll
        for (int j = 0; j < 8; j++) {
            int idx = tid + j * 256;            // 0..2047
            int arr = idx >> 9;                 // 0..3
            int t   = idx & 511;
            int r   = t >> 2, u = t & 3;        // row 0..127, 16B unit 0..3
            int grow = (arr < 2) ? (brow + r) : (bcol + r);
            const __nv_bfloat16* src = srcs[arr] + (size_t)grow * K + k0 + u * 8;
            CP_ASYNC16(st + (unsigned)(arr * ARR_B + r * ROW_B + u * 16), src);
        }
        CP_COMMIT();
    };

#pragma unroll
    for (int c = 0; c < GSTAGES; c++) fill_stage(c, c);

#pragma unroll 1
    for (int c = 0; c < nchunks; c++) {
        const int s = c % GSTAGES;
        const int rem = nchunks - 1 - c;
        if (rem >= 2)      asm volatile("cp.async.wait_group 2;" ::: "memory");
        else if (rem == 1) asm volatile("cp.async.wait_group 1;" ::: "memory");
        else               asm volatile("cp.async.wait_group 0;" ::: "memory");
        __syncthreads();

        const unsigned* sA0 = (const unsigned*)(gsm + s * STAGE_B);
        const unsigned* sA1 = (const unsigned*)(gsm + s * STAGE_B + ARR_B);
        const unsigned* sB0 = (const unsigned*)(gsm + s * STAGE_B + 2 * ARR_B);
        const unsigned* sB1 = (const unsigned*)(gsm + s * STAGE_B + 3 * ARR_B);
        const int ROW_W = ROW_B / 4;   // 20 words per row

#pragma unroll
        for (int ks = 0; ks < 2; ks++) {
            const int kw = ks * 8 + t4;          // word offset within row
            unsigned a0f[2][4], a1f[2][4];
#pragma unroll
            for (int mf = 0; mf < 2; mf++) {
                const int r0 = wm * 32 + mf * 16 + g;
                a0f[mf][0] = sA0[r0 * ROW_W + kw];
                a0f[mf][1] = sA0[(r0 + 8) * ROW_W + kw];
                a0f[mf][2] = sA0[r0 * ROW_W + kw + 4];
                a0f[mf][3] = sA0[(r0 + 8) * ROW_W + kw + 4];
                a1f[mf][0] = sA1[r0 * ROW_W + kw];
                a1f[mf][1] = sA1[(r0 + 8) * ROW_W + kw];
                a1f[mf][2] = sA1[r0 * ROW_W + kw + 4];
                a1f[mf][3] = sA1[(r0 + 8) * ROW_W + kw + 4];
            }
#pragma unroll
            for (int nf = 0; nf < 8; nf++) {
                const int n = wn * 64 + nf * 8 + g;
                unsigned b0f[2], b1f[2];
                b0f[0] = sB0[n * ROW_W + kw];
                b0f[1] = sB0[n * ROW_W + kw + 4];
                b1f[0] = sB1[n * ROW_W + kw];
                b1f[1] = sB1[n * ROW_W + kw + 4];
#pragma unroll
                for (int mf = 0; mf < 2; mf++) {
                    mma_bf16(acc[mf][nf], a0f[mf], b0f);
                    mma_bf16(acc[mf][nf], a0f[mf], b1f);
                    mma_bf16(acc[mf][nf], a1f[mf], b0f);
                }
            }
        }
        __syncthreads();

        if (c + GSTAGES < nchunks) fill_stage(c + GSTAGES, s);
    }

#pragma unroll
    for (int mf = 0; mf < 2; mf++) {
        const int r0 = brow + wm * 32 + mf * 16 + g;
#pragma unroll
        for (int nf = 0; nf < 8; nf++) {
            const int cc = bcol + wn * 64 + nf * 8 + 2 * t4;
            *(float2*)&C[(size_t)r0 * N + cc] =
                make_float2(acc[mf][nf][0], acc[mf][nf][1]);
            *(float2*)&C[(size_t)(r0 + 8) * N + cc] =
                make_float2(acc[mf][nf][2], acc[mf][nf][3]);
        }
    }
}

// ===========================================================================
// Fused RMSNorm (+ optional weight) + RoPE
// ===========================================================================
__global__ __launch_bounds__(256) void norm_rope_kernel(
    const float* __restrict__ qw, const float* __restrict__ kw,
    const float* __restrict__ cosb, const float* __restrict__ sinb)
{
    const int s    = blockIdx.x;
    const int slot = blockIdx.y;
    const int d    = threadIdx.x;

    float* basep;
    const float* w = nullptr;
    bool do_rope = true;
    if (slot < 8)       { basep = g_q + (size_t)s * (NHQ * DH) + slot * DH;        w = qw; }
    else if (slot < 10) { basep = g_k + (size_t)s * (NKV * DH) + (slot - 8) * DH;  w = kw; }
    else                { basep = g_v + (size_t)s * (NKV * DH) + (slot - 10) * DH; do_rope = false; }

    float x  = basep[d];
    float v2 = x * x;
#pragma unroll
    for (int o = 16; o > 0; o >>= 1) v2 += __shfl_xor_sync(0xffffffffu, v2, o);

    __shared__ float wsum[8];
    __shared__ float ys[256];
    const int warp = d >> 5, lane = d & 31;
    if (lane == 0) wsum[warp] = v2;
    __syncthreads();
    float tot = 0.f;
#pragma unroll
    for (int i = 0; i < 8; i++) tot += wsum[i];

    float y = x * rsqrtf(tot * (1.0f / 256.0f) + 1e-6f);
    if (w) y *= w[d];

    if (do_rope) {
        ys[d] = y;
        __syncthreads();
        float rot = (d < 128) ? -ys[d + 128] : ys[d - 128];
        y = y * cosb[(size_t)s * DH + d] + rot * sinb[(size_t)s * DH + d];
    }
    basep[d] = y;
}

// ===========================================================================
// Sliding-window causal attention (fp32) with boundary-tile loop bounds.
// ===========================================================================
__global__ __launch_bounds__(256) void attn_kernel(float* __restrict__ gout)
{
    extern __shared__ float sm[];
    float* Ks = sm;
    float* Vs = sm + 64 * 256;
    float* Sp = sm + 2 * 64 * 256;

    const int tid = threadIdx.x;
    const int qt  = blockIdx.x;
    const int h   = blockIdx.y;
    const int kvh = h >> 2;
    const int q0  = qt * 64;
    const int qi  = tid & 63;
    const int dg  = tid >> 6;
    const int qglob = q0 + qi;

    float qreg[64];
    {
        const float* qptr = g_q + (size_t)qglob * (NHQ * DH) + h * DH + dg * 64;
#pragma unroll
        for (int i = 0; i < 64; i += 4) {
            float4 t4 = *(const float4*)(qptr + i);
            qreg[i] = t4.x; qreg[i + 1] = t4.y; qreg[i + 2] = t4.z; qreg[i + 3] = t4.w;
        }
    }

    float acc[64];
#pragma unroll
    for (int i = 0; i < 64; i++) acc[i] = 0.f;
    float m = -1e30f, l = 0.f;

    const int t0 = max(0, qt - 8);
    for (int kt = t0; kt <= qt; kt++) {
        const int kbase = kt * 64;
        // valid kj range for this thread's query
        const int kj_lo = (kt == qt - 8) ? qi + 1 : 0;
        const int kj_hi = (kt == qt) ? qi : 63;

        for (int i = tid; i < 64 * 64; i += 256) {
            int row = i >> 6;
            int c4  = (i & 63) * 4;
            size_t goff = (size_t)(kbase + row) * (NKV * DH) + kvh * DH + c4;
            *(float4*)(Ks + row * 256 + c4) = *(const float4*)(g_k + goff);
            *(float4*)(Vs + row * 256 + c4) = *(const float4*)(g_v + goff);
        }
        __syncthreads();

        float* myp = Sp + dg * 64 * 64;
        for (int kj = kj_lo; kj <= kj_hi; kj++) {
            const float* kr = Ks + kj * 256 + dg * 64;
            float s0 = 0.f, s1 = 0.f, s2 = 0.f, s3 = 0.f;
#pragma unroll
            for (int i = 0; i < 64; i += 4) {
                float4 k4 = *(const float4*)(kr + i);
                s0 += qreg[i]     * k4.x;
                s1 += qreg[i + 1] * k4.y;
                s2 += qreg[i + 2] * k4.z;
                s3 += qreg[i + 3] * k4.w;
            }
            myp[kj * 64 + qi] = (s0 + s1) + (s2 + s3);
        }
        __syncthreads();

        for (int i = tid; i < 4096; i += 256) {
            float v = Sp[i] + Sp[4096 + i] + Sp[8192 + i] + Sp[12288 + i];
            int kj = i >> 6, qq = i & 63;
            int kk = kbase + kj, qg = q0 + qq;
            bool valid = (kk <= qg) && (qg - kk < WINDOW);
            Sp[i] = valid ? v : -1e30f;
        }
        __syncthreads();

        float mt = m;
        for (int kj = kj_lo; kj <= kj_hi; kj++) mt = fmaxf(mt, Sp[kj * 64 + qi]);
        float c = __expf(m - mt);
        m = mt;
        l *= c;
#pragma unroll
        for (int i = 0; i < 64; i++) acc[i] *= c;

        for (int kj = kj_lo; kj <= kj_hi; kj++) {
            float p = __expf(Sp[kj * 64 + qi] - mt);
            l += p;
            const float* vr = Vs + kj * 256 + dg * 64;
#pragma unroll
            for (int i = 0; i < 64; i += 4) {
                float4 v4 = *(const float4*)(vr + i);
                acc[i]     += p * v4.x;
                acc[i + 1] += p * v4.y;
                acc[i + 2] += p * v4.z;
                acc[i + 3] += p * v4.w;
            }
        }
        __syncthreads();
    }

    float inv_l = 1.f / l;
#pragma unroll
    for (int i = 0; i < 64; i++) Ks[qi * 256 + dg * 64 + i] = acc[i] * inv_l;
    __syncthreads();

    for (int i = tid; i < 64 * 64; i += 256) {
        int row = i >> 6;
        int c4  = (i & 63) * 4;
        *(float4*)(gout + (size_t)(q0 + row) * (NHQ * DH) + h * DH + c4) =
            *(const float4*)(Ks + row * 256 + c4);
    }
}

// ===========================================================================
extern "C" void kernel_launch(void* const* d_in, const int* in_sizes, int n_in,
                              void* d_out, int out_size)
{
    (void)in_sizes; (void)n_in; (void)out_size;
    const float* hs   = (const float*)d_in[0];
    const float* w_q  = (const float*)d_in[1];
    const float* w_k  = (const float*)d_in[2];
    const float* w_v  = (const float*)d_in[3];
    const float* w_o  = (const float*)d_in[4];
    const float* qw   = (const float*)d_in[5];
    const float* kw   = (const float*)d_in[6];
    const float* cosb = (const float*)d_in[7];
    const float* sinb = (const float*)d_in[8];
    float* out = (float*)d_out;

    float *gq, *gk, *gv, *ga;
    __nv_bfloat16 *a0, *a1, *wq0, *wq1, *wk0, *wk1, *wv0, *wv1, *wo0, *wo1;
    cudaGetSymbolAddress((void**)&gq, g_q);
    cudaGetSymbolAddress((void**)&gk, g_k);
    cudaGetSymbolAddress((void**)&gv, g_v);
    cudaGetSymbolAddress((void**)&ga, g_attn);
    cudaGetSymbolAddress((void**)&a0, g_a0);
    cudaGetSymbolAddress((void**)&a1, g_a1);
    cudaGetSymbolAddress((void**)&wq0, g_wq0);
    cudaGetSymbolAddress((void**)&wq1, g_wq1);
    cudaGetSymbolAddress((void**)&wk0, g_wk0);
    cudaGetSymbolAddress((void**)&wk1, g_wk1);
    cudaGetSymbolAddress((void**)&wv0, g_wv0);
    cudaGetSymbolAddress((void**)&wv1, g_wv1);
    cudaGetSymbolAddress((void**)&wo0, g_wo0);
    cudaGetSymbolAddress((void**)&wo1, g_wo1);

    const int attn_smem = (2 * 64 * 256 + 4 * 64 * 64) * sizeof(float);
    cudaFuncSetAttribute(bf16_gemm_kernel, cudaFuncAttributeMaxDynamicSharedMemorySize, GEMM_SMEM);
    cudaFuncSetAttribute(attn_kernel, cudaFuncAttributeMaxDynamicSharedMemorySize, attn_smem);

    // --- pre-pass: bf16 hi/lo splits ---
    split_kernel<<<(S_LEN * HDIM / 4 + 255) / 256, 256>>>(hs, a0, a1, S_LEN * HDIM);
    tsplit_kernel<<<dim3(HDIM / 32, HDIM / 32), dim3(32, 8)>>>(w_q, wq0, wq1, HDIM, HDIM);
    tsplit_kernel<<<dim3((NKV * DH) / 32, HDIM / 32), dim3(32, 8)>>>(w_k, wk0, wk1, HDIM, NKV * DH);
    tsplit_kernel<<<dim3((NKV * DH) / 32, HDIM / 32), dim3(32, 8)>>>(w_v, wv0, wv1, HDIM, NKV * DH);
    tsplit_kernel<<<dim3(HDIM / 32, HDIM / 32), dim3(32, 8)>>>(w_o, wo0, wo1, HDIM, HDIM);

    // --- QKV projections (bf16x3 mma) ---
    bf16_gemm_kernel<<<dim3((NHQ * DH) / 128, S_LEN / 128), 256, GEMM_SMEM>>>(
        a0, a1, wq0, wq1, gq, S_LEN, NHQ * DH, HDIM);
    bf16_gemm_kernel<<<dim3((NKV * DH) / 128, S_LEN / 128), 256, GEMM_SMEM>>>(
        a0, a1, wk0, wk1, gk, S_LEN, NKV * DH, HDIM);
    bf16_gemm_kernel<<<dim3((NKV * DH) / 128, S_LEN / 128), 256, GEMM_SMEM>>>(
        a0, a1, wv0, wv1, gv, S_LEN, NKV * DH, HDIM);

    // --- RMSNorm + RoPE ---
    norm_rope_kernel<<<dim3(S_LEN, NHQ + 2 * NKV), 256>>>(qw, kw, cosb, sinb);

    // --- Sliding-window attention ---
    attn_kernel<<<dim3(S_LEN / 64, NHQ), 256, attn_smem>>>(ga);

    // --- split attention output, O-projection ---
    split_kernel<<<(S_LEN * HDIM / 4 + 255) / 256, 256>>>(ga, a0, a1, S_LEN * HDIM);
    bf16_gemm_kernel<<<dim3(HDIM / 128, S_LEN / 128), 256, GEMM_SMEM>>>(
        a0, a1, wo0, wo1, out, S_LEN, HDIM, HDIM);
}

// round 6
// speedup vs baseline: 2.6751x; 1.7761x over previous
#include <cuda_runtime.h>
#include <cuda_bf16.h>
#include <math.h>

#define S_LEN  4096
#define HDIM   2048
#define NHQ    8
#define NKV    2
#define DH     256
#define WINDOW 512

// fp32 scratch
__device__ float g_q[S_LEN * NHQ * DH];     // 32 MB
__device__ float g_k[S_LEN * NKV * DH];     // 8 MB
__device__ float g_v[S_LEN * NKV * DH];     // 8 MB
__device__ float g_attn[S_LEN * NHQ * DH];  // 32 MB

// bf16 split scratch. g_a* reused: hs splits -> q splits -> attn-out splits.
__device__ __nv_bfloat16 g_a0[S_LEN * HDIM];        // 16 MB
__device__ __nv_bfloat16 g_a1[S_LEN * HDIM];        // 16 MB
__device__ __nv_bfloat16 g_wq0[HDIM * HDIM];
__device__ __nv_bfloat16 g_wq1[HDIM * HDIM];
__device__ __nv_bfloat16 g_wk0[(NKV * DH) * HDIM];
__device__ __nv_bfloat16 g_wk1[(NKV * DH) * HDIM];
__device__ __nv_bfloat16 g_wv0[(NKV * DH) * HDIM];
__device__ __nv_bfloat16 g_wv1[(NKV * DH) * HDIM];
__device__ __nv_bfloat16 g_wo0[HDIM * HDIM];
__device__ __nv_bfloat16 g_wo1[HDIM * HDIM];
// attention operand splits
__device__ __nv_bfloat16 g_k0s[S_LEN * NKV * DH];   // 4 MB
__device__ __nv_bfloat16 g_k1s[S_LEN * NKV * DH];
__device__ __nv_bfloat16 g_vt0[NKV * DH * S_LEN];   // [h][d][s]
__device__ __nv_bfloat16 g_vt1[NKV * DH * S_LEN];

// ===========================================================================
// Helpers
// ===========================================================================
__device__ __forceinline__ unsigned smem_u32(const void* p) {
    unsigned a;
    asm("{ .reg .u64 t; cvta.to.shared.u64 t, %1; cvt.u32.u64 %0, t; }"
        : "=r"(a) : "l"(p));
    return a;
}

#define CP_ASYNC16(dst, src) \
    asm volatile("cp.async.cg.shared.global [%0], [%1], 16;" :: "r"(dst), "l"(src) : "memory")
#define CP_COMMIT() asm volatile("cp.async.commit_group;" ::: "memory")

__device__ __forceinline__ void bf16_split(float x, __nv_bfloat16& h, __nv_bfloat16& l) {
    h = __float2bfloat16_rn(x);
    l = __float2bfloat16_rn(x - __bfloat162float(h));
}

__device__ __forceinline__ unsigned bpack(__nv_bfloat16 x, __nv_bfloat16 y) {
    unsigned short xb = __bfloat16_as_ushort(x), yb = __bfloat16_as_ushort(y);
    return ((unsigned)yb << 16) | (unsigned)xb;
}

__device__ __forceinline__ void mma_bf16(float* d, const unsigned* a, const unsigned* b) {
    asm volatile(
        "mma.sync.aligned.m16n8k16.row.col.f32.bf16.bf16.f32 "
        "{%0,%1,%2,%3}, {%4,%5,%6,%7}, {%8,%9}, {%0,%1,%2,%3};"
        : "+f"(d[0]), "+f"(d[1]), "+f"(d[2]), "+f"(d[3])
        : "r"(a[0]), "r"(a[1]), "r"(a[2]), "r"(a[3]), "r"(b[0]), "r"(b[1]));
}

// ===========================================================================
// Split kernel: fp32 [n] -> hi/lo bf16 planar. 4 elems/thread.
// ===========================================================================
__global__ __launch_bounds__(256) void split_kernel(
    const float* __restrict__ in, __nv_bfloat16* __restrict__ o0,
    __nv_bfloat16* __restrict__ o1, int n)
{
    int i = (blockIdx.x * 256 + threadIdx.x) * 4;
    if (i >= n) return;
    float4 v = *(const float4*)(in + i);
    __nv_bfloat16 h0, l0, h1, l1, h2, l2, h3, l3;
    bf16_split(v.x, h0, l0); bf16_split(v.y, h1, l1);
    bf16_split(v.z, h2, l2); bf16_split(v.w, h3, l3);
    __nv_bfloat162* p0 = (__nv_bfloat162*)(o0 + i);
    __nv_bfloat162* p1 = (__nv_bfloat162*)(o1 + i);
    p0[0] = __nv_bfloat162(h0, h1); p0[1] = __nv_bfloat162(h2, h3);
    p1[0] = __nv_bfloat162(l0, l1); p1[1] = __nv_bfloat162(l2, l3);
}

// ===========================================================================
// Transpose-split kernel (weights): fp32 B [K][N] -> hi/lo bf16 [N][K].
// ===========================================================================
__global__ __launch_bounds__(256) void tsplit_kernel(
    const float* __restrict__ in, __nv_bfloat16* __restrict__ o0,
    __nv_bfloat16* __restrict__ o1, int K, int N)
{
    __shared__ float tile[32][33];
    const int n0 = blockIdx.x * 32;
    const int k0 = blockIdx.y * 32;
    const int tx = threadIdx.x, ty = threadIdx.y;
#pragma unroll
    for (int j = 0; j < 4; j++)
        tile[ty + 8 * j][tx] = in[(size_t)(k0 + ty + 8 * j) * N + n0 + tx];
    __syncthreads();
#pragma unroll
    for (int j = 0; j < 4; j++) {
        int ny = ty + 8 * j;
        float x = tile[tx][ny];
        __nv_bfloat16 h, l;
        bf16_split(x, h, l);
        size_t off = (size_t)(n0 + ny) * K + k0 + tx;
        o0[off] = h;
        o1[off] = l;
    }
}

// ===========================================================================
// V transpose-split: g_v [S][NKV*DH] -> vt [h][DH][S] hi/lo bf16.
// grid (S/32, DH/32, NKV), block (32, 8)
// ===========================================================================
__global__ __launch_bounds__(256) void vsplit_t_kernel(
    const float* __restrict__ in, __nv_bfloat16* __restrict__ o0,
    __nv_bfloat16* __restrict__ o1)
{
    __shared__ float tile[32][33];
    const int s0 = blockIdx.x * 32;
    const int d0 = blockIdx.y * 32;
    const int hh = blockIdx.z;
    const int tx = threadIdx.x, ty = threadIdx.y;
#pragma unroll
    for (int j = 0; j < 4; j++)
        tile[ty + 8 * j][tx] = in[(size_t)(s0 + ty + 8 * j) * (NKV * DH) + hh * DH + d0 + tx];
    __syncthreads();
#pragma unroll
    for (int j = 0; j < 4; j++) {
        int dy = ty + 8 * j;
        float x = tile[tx][dy];       // (s = s0+tx, d = d0+dy)
        __nv_bfloat16 h, l;
        bf16_split(x, h, l);
        size_t off = (size_t)(hh * DH + d0 + dy) * S_LEN + s0 + tx;
        o0[off] = h;
        o1[off] = l;
    }
}

// ===========================================================================
// bf16x3 GEMM (unchanged from R5)
// ===========================================================================
#define ROW_E   40
#define ROW_B   (ROW_E * 2)
#define ARR_B   (128 * ROW_B)
#define STAGE_B (4 * ARR_B)
#define GSTAGES 3
#define GEMM_SMEM (GSTAGES * STAGE_B)

__global__ __launch_bounds__(256) void bf16_gemm_kernel(
    const __nv_bfloat16* __restrict__ A0, const __nv_bfloat16* __restrict__ A1,
    const __nv_bfloat16* __restrict__ B0, const __nv_bfloat16* __restrict__ B1,
    float* __restrict__ C, int M, int N, int K)
{
    extern __shared__ char gsm[];
    const unsigned sbase = smem_u32(gsm);

    const int tid  = threadIdx.x;
    const int wid  = tid >> 5;
    const int lane = tid & 31;
    const int g    = lane >> 2;
    const int t4   = lane & 3;
    const int wm   = wid & 3;
    const int wn   = wid >> 2;

    const int brow = blockIdx.y * 128;
    const int bcol = blockIdx.x * 128;
    const int nchunks = K / 32;

    float acc[2][8][4];
#pragma unroll
    for (int mf = 0; mf < 2; mf++)
#pragma unroll
        for (int nf = 0; nf < 8; nf++)
#pragma unroll
            for (int r = 0; r < 4; r++) acc[mf][nf][r] = 0.f;

    const __nv_bfloat16* srcs[4] = {A0, A1, B0, B1};

    auto fill_stage = [&](int c, int s) {
        const int k0 = c * 32;
        const unsigned st = sbase + s * STAGE_B;
#pragma unroll
        for (int j = 0; j < 8; j++) {
            int idx = tid + j * 256;
            int arr = idx >> 9;
            int t   = idx & 511;
            int r   = t >> 2, u = t & 3;
            int grow = (arr < 2) ? (brow + r) : (bcol + r);
            const __nv_bfloat16* src = srcs[arr] + (size_t)grow * K + k0 + u * 8;
            CP_ASYNC16(st + (unsigned)(arr * ARR_B + r * ROW_B + u * 16), src);
        }
        CP_COMMIT();
    };

#pragma unroll
    for (int c = 0; c < GSTAGES; c++) fill_stage(c, c);

#pragma unroll 1
    for (int c = 0; c < nchunks; c++) {
        const int s = c % GSTAGES;
        const int rem = nchunks - 1 - c;
        if (rem >= 2)      asm volatile("cp.async.wait_group 2;" ::: "memory");
        else if (rem == 1) asm volatile("cp.async.wait_group 1;" ::: "memory");
        else               asm volatile("cp.async.wait_group 0;" ::: "memory");
        __syncthreads();

        const unsigned* sA0 = (const unsigned*)(gsm + s * STAGE_B);
        const unsigned* sA1 = (const unsigned*)(gsm + s * STAGE_B + ARR_B);
        const unsigned* sB0 = (const unsigned*)(gsm + s * STAGE_B + 2 * ARR_B);
        const unsigned* sB1 = (const unsigned*)(gsm + s * STAGE_B + 3 * ARR_B);
        const int ROW_W = ROW_B / 4;

#pragma unroll
        for (int ks = 0; ks < 2; ks++) {
            const int kw = ks * 8 + t4;
            unsigned a0f[2][4], a1f[2][4];
#pragma unroll
            for (int mf = 0; mf < 2; mf++) {
                const int r0 = wm * 32 + mf * 16 + g;
                a0f[mf][0] = sA0[r0 * ROW_W + kw];
                a0f[mf][1] = sA0[(r0 + 8) * ROW_W + kw];
                a0f[mf][2] = sA0[r0 * ROW_W + kw + 4];
                a0f[mf][3] = sA0[(r0 + 8) * ROW_W + kw + 4];
                a1f[mf][0] = sA1[r0 * ROW_W + kw];
                a1f[mf][1] = sA1[(r0 + 8) * ROW_W + kw];
                a1f[mf][2] = sA1[r0 * ROW_W + kw + 4];
                a1f[mf][3] = sA1[(r0 + 8) * ROW_W + kw + 4];
            }
#pragma unroll
            for (int nf = 0; nf < 8; nf++) {
                const int n = wn * 64 + nf * 8 + g;
                unsigned b0f[2], b1f[2];
                b0f[0] = sB0[n * ROW_W + kw];
                b0f[1] = sB0[n * ROW_W + kw + 4];
                b1f[0] = sB1[n * ROW_W + kw];
                b1f[1] = sB1[n * ROW_W + kw + 4];
#pragma unroll
                for (int mf = 0; mf < 2; mf++) {
                    mma_bf16(acc[mf][nf], a0f[mf], b0f);
                    mma_bf16(acc[mf][nf], a0f[mf], b1f);
                    mma_bf16(acc[mf][nf], a1f[mf], b0f);
                }
            }
        }
        __syncthreads();

        if (c + GSTAGES < nchunks) fill_stage(c + GSTAGES, s);
    }

#pragma unroll
    for (int mf = 0; mf < 2; mf++) {
        const int r0 = brow + wm * 32 + mf * 16 + g;
#pragma unroll
        for (int nf = 0; nf < 8; nf++) {
            const int cc = bcol + wn * 64 + nf * 8 + 2 * t4;
            *(float2*)&C[(size_t)r0 * N + cc] =
                make_float2(acc[mf][nf][0], acc[mf][nf][1]);
            *(float2*)&C[(size_t)(r0 + 8) * N + cc] =
                make_float2(acc[mf][nf][2], acc[mf][nf][3]);
        }
    }
}

// ===========================================================================
// Fused RMSNorm (+ optional weight) + RoPE
// ===========================================================================
__global__ __launch_bounds__(256) void norm_rope_kernel(
    const float* __restrict__ qw, const float* __restrict__ kw,
    const float* __restrict__ cosb, const float* __restrict__ sinb)
{
    const int s    = blockIdx.x;
    const int slot = blockIdx.y;
    const int d    = threadIdx.x;

    float* basep;
    const float* w = nullptr;
    bool do_rope = true;
    if (slot < 8)       { basep = g_q + (size_t)s * (NHQ * DH) + slot * DH;        w = qw; }
    else if (slot < 10) { basep = g_k + (size_t)s * (NKV * DH) + (slot - 8) * DH;  w = kw; }
    else                { basep = g_v + (size_t)s * (NKV * DH) + (slot - 10) * DH; do_rope = false; }

    float x  = basep[d];
    float v2 = x * x;
#pragma unroll
    for (int o = 16; o > 0; o >>= 1) v2 += __shfl_xor_sync(0xffffffffu, v2, o);

    __shared__ float wsum[8];
    __shared__ float ys[256];
    const int warp = d >> 5, lane = d & 31;
    if (lane == 0) wsum[warp] = v2;
    __syncthreads();
    float tot = 0.f;
#pragma unroll
    for (int i = 0; i < 8; i++) tot += wsum[i];

    float y = x * rsqrtf(tot * (1.0f / 256.0f) + 1e-6f);
    if (w) y *= w[d];

    if (do_rope) {
        ys[d] = y;
        __syncthreads();
        float rot = (d < 128) ? -ys[d + 128] : ys[d - 128];
        y = y * cosb[(size_t)s * DH + d] + rot * sinb[(size_t)s * DH + d];
    }
    basep[d] = y;
}

// ===========================================================================
// MMA flash attention (bf16x3). grid (S/64, NHQ), block 128 (4 warps).
// Warp w owns q-rows 16w..16w+15. Scores m16n64 k256, PV m16n256 k64.
// SMEM (32-bit words): Q0/Q1 [64][132], K0/K1 [64][132], VT0/VT1 [256][36]
// ===========================================================================
#define QROWW 132
#define VROWW 36
#define QW0_OFF 0
#define QW1_OFF (64 * QROWW)
#define KW0_OFF (2 * 64 * QROWW)
#define KW1_OFF (3 * 64 * QROWW)
#define VW0_OFF (4 * 64 * QROWW)
#define VW1_OFF (4 * 64 * QROWW + 256 * VROWW)
#define ATTN_SMEM_BYTES ((4 * 64 * QROWW + 2 * 256 * VROWW) * 4)   // 208896

__global__ __launch_bounds__(128, 1) void attn_mma_kernel(
    const __nv_bfloat16* __restrict__ q0, const __nv_bfloat16* __restrict__ q1,
    const __nv_bfloat16* __restrict__ k0, const __nv_bfloat16* __restrict__ k1,
    const __nv_bfloat16* __restrict__ vt0, const __nv_bfloat16* __restrict__ vt1,
    float* __restrict__ gout)
{
    extern __shared__ unsigned smw[];
    const unsigned sbase = smem_u32(smw);
    const int tid = threadIdx.x;
    const int w = tid >> 5, lane = tid & 31;
    const int g = lane >> 2, t4 = lane & 3;
    const int qt = blockIdx.x, h = blockIdx.y, kvh = h >> 2;
    const int q0r = qt * 64;

    // Q load (once): 2 arrays x 64 rows x 32 units
#pragma unroll 4
    for (int j = 0; j < 32; j++) {
        int idx = tid + j * 128;
        int arr = idx >> 11, t = idx & 2047;
        int r = t >> 5, u = t & 31;
        const __nv_bfloat16* src = (arr ? q1 : q0) + (size_t)(q0r + r) * 2048 + h * 256 + u * 8;
        unsigned dst = sbase + (unsigned)(((arr ? QW1_OFF : QW0_OFF) + r * QROWW + u * 4) * 4);
        CP_ASYNC16(dst, src);
    }
    CP_COMMIT();

    float o[32][4];
#pragma unroll
    for (int nf = 0; nf < 32; nf++)
#pragma unroll
        for (int r = 0; r < 4; r++) o[nf][r] = 0.f;
    float m_g = -1e30f, m_g8 = -1e30f, l_g = 0.f, l_g8 = 0.f;

    const unsigned* QW0 = smw + QW0_OFF;
    const unsigned* QW1 = smw + QW1_OFF;
    const unsigned* KW0 = smw + KW0_OFF;
    const unsigned* KW1 = smw + KW1_OFF;
    const unsigned* VW0 = smw + VW0_OFF;
    const unsigned* VW1 = smw + VW1_OFF;

    const int qg_g  = q0r + 16 * w + g;
    const int qg_g8 = qg_g + 8;

    const int t0 = max(0, qt - 8);
#pragma unroll 1
    for (int kt = t0; kt <= qt; kt++) {
        const int kbase = kt * 64;
        __syncthreads();   // previous compute done before overwriting K/V

        // K tiles (group A)
#pragma unroll 4
        for (int j = 0; j < 32; j++) {
            int idx = tid + j * 128;
            int arr = idx >> 11, t = idx & 2047;
            int r = t >> 5, u = t & 31;
            const __nv_bfloat16* src = (arr ? k1 : k0) + (size_t)(kbase + r) * 512 + kvh * 256 + u * 8;
            unsigned dst = sbase + (unsigned)(((arr ? KW1_OFF : KW0_OFF) + r * QROWW + u * 4) * 4);
            CP_ASYNC16(dst, src);
        }
        CP_COMMIT();
        // V tiles (group B) - overlaps with score compute
#pragma unroll 4
        for (int j = 0; j < 32; j++) {
            int idx = tid + j * 128;
            int arr = idx >> 11, t = idx & 2047;
            int r = t >> 3, u = t & 7;
            const __nv_bfloat16* src = (arr ? vt1 : vt0) + (size_t)(kvh * 256 + r) * 4096 + kbase + u * 8;
            unsigned dst = sbase + (unsigned)(((arr ? VW1_OFF : VW0_OFF) + r * VROWW + u * 4) * 4);
            CP_ASYNC16(dst, src);
        }
        CP_COMMIT();

        asm volatile("cp.async.wait_group 1;" ::: "memory");  // Q(+prev) + K ready
        __syncthreads();

        // ---- scores S[16][64] ----
        float sc[8][4];
#pragma unroll
        for (int nf = 0; nf < 8; nf++)
#pragma unroll
            for (int r = 0; r < 4; r++) sc[nf][r] = 0.f;

#pragma unroll
        for (int ks = 0; ks < 16; ks++) {
            const int ra = (16 * w + g) * QROWW + 8 * ks + t4;
            const int rb = ra + 8 * QROWW;
            unsigned aH[4], aL[4];
            aH[0] = QW0[ra]; aH[1] = QW0[rb]; aH[2] = QW0[ra + 4]; aH[3] = QW0[rb + 4];
            aL[0] = QW1[ra]; aL[1] = QW1[rb]; aL[2] = QW1[ra + 4]; aL[3] = QW1[rb + 4];
#pragma unroll
            for (int nf = 0; nf < 8; nf++) {
                const int kb = (nf * 8 + g) * QROWW + 8 * ks + t4;
                unsigned bH[2] = {KW0[kb], KW0[kb + 4]};
                unsigned bL[2] = {KW1[kb], KW1[kb + 4]};
                mma_bf16(sc[nf], aH, bH);
                mma_bf16(sc[nf], aH, bL);
                mma_bf16(sc[nf], aL, bH);
            }
        }

        // ---- mask ----
#pragma unroll
        for (int nf = 0; nf < 8; nf++) {
            const int c0 = kbase + nf * 8 + 2 * t4;
            const int c1 = c0 + 1;
            if (!(c0 <= qg_g  && qg_g  - c0 < WINDOW)) sc[nf][0] = -1e30f;
            if (!(c1 <= qg_g  && qg_g  - c1 < WINDOW)) sc[nf][1] = -1e30f;
            if (!(c0 <= qg_g8 && qg_g8 - c0 < WINDOW)) sc[nf][2] = -1e30f;
            if (!(c1 <= qg_g8 && qg_g8 - c1 < WINDOW)) sc[nf][3] = -1e30f;
        }

        // ---- online softmax ----
        float mx0 = -1e30f, mx1 = -1e30f;
#pragma unroll
        for (int nf = 0; nf < 8; nf++) {
            mx0 = fmaxf(mx0, fmaxf(sc[nf][0], sc[nf][1]));
            mx1 = fmaxf(mx1, fmaxf(sc[nf][2], sc[nf][3]));
        }
        mx0 = fmaxf(mx0, __shfl_xor_sync(0xffffffffu, mx0, 1));
        mx0 = fmaxf(mx0, __shfl_xor_sync(0xffffffffu, mx0, 2));
        mx1 = fmaxf(mx1, __shfl_xor_sync(0xffffffffu, mx1, 1));
        mx1 = fmaxf(mx1, __shfl_xor_sync(0xffffffffu, mx1, 2));

        const float mn0 = fmaxf(m_g, mx0), mn1 = fmaxf(m_g8, mx1);
        const float s0 = __expf(m_g - mn0), s1 = __expf(m_g8 - mn1);
        m_g = mn0; m_g8 = mn1;

        float ls0 = 0.f, ls1 = 0.f;
#pragma unroll
        for (int nf = 0; nf < 8; nf++) {
            sc[nf][0] = __expf(sc[nf][0] - mn0);
            sc[nf][1] = __expf(sc[nf][1] - mn0);
            sc[nf][2] = __expf(sc[nf][2] - mn1);
            sc[nf][3] = __expf(sc[nf][3] - mn1);
            ls0 += sc[nf][0] + sc[nf][1];
            ls1 += sc[nf][2] + sc[nf][3];
        }
        ls0 += __shfl_xor_sync(0xffffffffu, ls0, 1);
        ls0 += __shfl_xor_sync(0xffffffffu, ls0, 2);
        ls1 += __shfl_xor_sync(0xffffffffu, ls1, 1);
        ls1 += __shfl_xor_sync(0xffffffffu, ls1, 2);
        l_g  = l_g  * s0 + ls0;
        l_g8 = l_g8 * s1 + ls1;

#pragma unroll
        for (int nf = 0; nf < 32; nf++) {
            o[nf][0] *= s0; o[nf][1] *= s0;
            o[nf][2] *= s1; o[nf][3] *= s1;
        }

        asm volatile("cp.async.wait_group 0;" ::: "memory");   // V ready
        __syncthreads();

        // ---- PV: O += P @ V, P from registers ----
#pragma unroll
        for (int s = 0; s < 4; s++) {
            unsigned aH[4], aL[4];
#pragma unroll
            for (int half = 0; half < 2; half++) {
                const float* pv = sc[2 * s + half];
                __nv_bfloat16 h0, l0, h1, l1, h2, l2, h3, l3;
                bf16_split(pv[0], h0, l0); bf16_split(pv[1], h1, l1);
                bf16_split(pv[2], h2, l2); bf16_split(pv[3], h3, l3);
                aH[2 * half]     = bpack(h0, h1);
                aH[2 * half + 1] = bpack(h2, h3);
                aL[2 * half]     = bpack(l0, l1);
                aL[2 * half + 1] = bpack(l2, l3);
            }
#pragma unroll
            for (int nf = 0; nf < 32; nf++) {
                const int vb = (nf * 8 + g) * VROWW + 8 * s + t4;
                unsigned bH[2] = {VW0[vb], VW0[vb + 4]};
                unsigned bL[2] = {VW1[vb], VW1[vb + 4]};
                mma_bf16(o[nf], aH, bH);
                mma_bf16(o[nf], aH, bL);
                mma_bf16(o[nf], aL, bH);
            }
        }
    }

    // ---- epilogue ----
    const float i0 = 1.f / l_g, i1 = 1.f / l_g8;
    const int colb = h * 256 + 2 * t4;
#pragma unroll
    for (int nf = 0; nf < 32; nf++) {
        const int cc = colb + nf * 8;
        *(float2*)&gout[(size_t)qg_g  * 2048 + cc] = make_float2(o[nf][0] * i0, o[nf][1] * i0);
        *(float2*)&gout[(size_t)qg_g8 * 2048 + cc] = make_float2(o[nf][2] * i1, o[nf][3] * i1);
    }
}

// ===========================================================================
extern "C" void kernel_launch(void* const* d_in, const int* in_sizes, int n_in,
                              void* d_out, int out_size)
{
    (void)in_sizes; (void)n_in; (void)out_size;
    const float* hs   = (const float*)d_in[0];
    const float* w_q  = (const float*)d_in[1];
    const float* w_k  = (const float*)d_in[2];
    const float* w_v  = (const float*)d_in[3];
    const float* w_o  = (const float*)d_in[4];
    const float* qw   = (const float*)d_in[5];
    const float* kw   = (const float*)d_in[6];
    const float* cosb = (const float*)d_in[7];
    const float* sinb = (const float*)d_in[8];
    float* out = (float*)d_out;

    float *gq, *gk, *gv, *ga;
    __nv_bfloat16 *a0, *a1, *wq0, *wq1, *wk0, *wk1, *wv0, *wv1, *wo0, *wo1;
    __nv_bfloat16 *k0s, *k1s, *vt0, *vt1;
    cudaGetSymbolAddress((void**)&gq, g_q);
    cudaGetSymbolAddress((void**)&gk, g_k);
    cudaGetSymbolAddress((void**)&gv, g_v);
    cudaGetSymbolAddress((void**)&ga, g_attn);
    cudaGetSymbolAddress((void**)&a0, g_a0);
    cudaGetSymbolAddress((void**)&a1, g_a1);
    cudaGetSymbolAddress((void**)&wq0, g_wq0);
    cudaGetSymbolAddress((void**)&wq1, g_wq1);
    cudaGetSymbolAddress((void**)&wk0, g_wk0);
    cudaGetSymbolAddress((void**)&wk1, g_wk1);
    cudaGetSymbolAddress((void**)&wv0, g_wv0);
    cudaGetSymbolAddress((void**)&wv1, g_wv1);
    cudaGetSymbolAddress((void**)&wo0, g_wo0);
    cudaGetSymbolAddress((void**)&wo1, g_wo1);
    cudaGetSymbolAddress((void**)&k0s, g_k0s);
    cudaGetSymbolAddress((void**)&k1s, g_k1s);
    cudaGetSymbolAddress((void**)&vt0, g_vt0);
    cudaGetSymbolAddress((void**)&vt1, g_vt1);

    cudaFuncSetAttribute(bf16_gemm_kernel, cudaFuncAttributeMaxDynamicSharedMemorySize, GEMM_SMEM);
    cudaFuncSetAttribute(attn_mma_kernel, cudaFuncAttributeMaxDynamicSharedMemorySize, ATTN_SMEM_BYTES);

    // --- pre-pass: bf16 hi/lo splits of inputs/weights ---
    split_kernel<<<(S_LEN * HDIM / 4 + 255) / 256, 256>>>(hs, a0, a1, S_LEN * HDIM);
    tsplit_kernel<<<dim3(HDIM / 32, HDIM / 32), dim3(32, 8)>>>(w_q, wq0, wq1, HDIM, HDIM);
    tsplit_kernel<<<dim3((NKV * DH) / 32, HDIM / 32), dim3(32, 8)>>>(w_k, wk0, wk1, HDIM, NKV * DH);
    tsplit_kernel<<<dim3((NKV * DH) / 32, HDIM / 32), dim3(32, 8)>>>(w_v, wv0, wv1, HDIM, NKV * DH);
    tsplit_kernel<<<dim3(HDIM / 32, HDIM / 32), dim3(32, 8)>>>(w_o, wo0, wo1, HDIM, HDIM);

    // --- QKV projections ---
    bf16_gemm_kernel<<<dim3((NHQ * DH) / 128, S_LEN / 128), 256, GEMM_SMEM>>>(
        a0, a1, wq0, wq1, gq, S_LEN, NHQ * DH, HDIM);
    bf16_gemm_kernel<<<dim3((NKV * DH) / 128, S_LEN / 128), 256, GEMM_SMEM>>>(
        a0, a1, wk0, wk1, gk, S_LEN, NKV * DH, HDIM);
    bf16_gemm_kernel<<<dim3((NKV * DH) / 128, S_LEN / 128), 256, GEMM_SMEM>>>(
        a0, a1, wv0, wv1, gv, S_LEN, NKV * DH, HDIM);

    // --- RMSNorm + RoPE ---
    norm_rope_kernel<<<dim3(S_LEN, NHQ + 2 * NKV), 256>>>(qw, kw, cosb, sinb);

    // --- split q/k, transpose-split v ---
    split_kernel<<<(S_LEN * HDIM / 4 + 255) / 256, 256>>>(gq, a0, a1, S_LEN * HDIM);
    split_kernel<<<(S_LEN * NKV * DH / 4 + 255) / 256, 256>>>(gk, k0s, k1s, S_LEN * NKV * DH);
    vsplit_t_kernel<<<dim3(S_LEN / 32, DH / 32, NKV), dim3(32, 8)>>>(gv, vt0, vt1);

    // --- MMA flash attention ---
    attn_mma_kernel<<<dim3(S_LEN / 64, NHQ), 128, ATTN_SMEM_BYTES>>>(
        a0, a1, k0s, k1s, vt0, vt1, ga);

    // --- split attention output, O-projection ---
    split_kernel<<<(S_LEN * HDIM / 4 + 255) / 256, 256>>>(ga, a0, a1, S_LEN * HDIM);
    bf16_gemm_kernel<<<dim3(HDIM / 128, S_LEN / 128), 256, GEMM_SMEM>>>(
        a0, a1, wo0, wo1, out, S_LEN, HDIM, HDIM);
}